// round 3
// baseline (speedup 1.0000x reference)
#include <cuda_runtime.h>
#include <cuda_fp16.h>
#include <cuda_bf16.h>

// Problem constants (from reference_code)
#define N_PATHS  10000000
#define MAX_LEN  3
#define N_NODES  100000
#define HIDDEN   128

// Number of nodes whose projections live in shared memory (fp16, planar).
// 3 planes * NS * 2B = 228000 B <= 227 KB max dynamic smem per CTA.
#define NS       38000
#define SMEM_BYTES (3 * NS * 2)

// Full-precision projection table (interleaved): proj[node*3 + l]
__device__ float  g_proj[N_NODES * MAX_LEN];
// fp16 planar copy of the first NS nodes: g16[l*NS + node]
__device__ __half g16[MAX_LEN * NS];

// ---------------------------------------------------------------------------
// Kernel 1: proj[node][l] = dot(feature[node], W[l][0]); also fp16 planar copy
// One warp per node; lane t covers dims [4t,4t+4) via float4.
// ---------------------------------------------------------------------------
__global__ void proj_kernel(const float* __restrict__ nf,
                            const float* __restrict__ W) {
    const int lane   = threadIdx.x & 31;
    const int warpIn = threadIdx.x >> 5;
    const int node   = blockIdx.x * (blockDim.x >> 5) + warpIn;
    if (node >= N_NODES) return;

    const float4 w0 = __ldg(((const float4*)W) + 0  + lane);
    const float4 w1 = __ldg(((const float4*)W) + 32 + lane);
    const float4 w2 = __ldg(((const float4*)W) + 64 + lane);

    const float4 f = __ldg(((const float4*)nf) + (size_t)node * 32 + lane);

    float s0 = f.x * w0.x + f.y * w0.y + f.z * w0.z + f.w * w0.w;
    float s1 = f.x * w1.x + f.y * w1.y + f.z * w1.z + f.w * w1.w;
    float s2 = f.x * w2.x + f.y * w2.y + f.z * w2.z + f.w * w2.w;

    #pragma unroll
    for (int o = 16; o > 0; o >>= 1) {
        s0 += __shfl_xor_sync(0xFFFFFFFFu, s0, o);
        s1 += __shfl_xor_sync(0xFFFFFFFFu, s1, o);
        s2 += __shfl_xor_sync(0xFFFFFFFFu, s2, o);
    }

    if (lane == 0) {
        g_proj[node * 3 + 0] = s0;
        g_proj[node * 3 + 1] = s1;
        g_proj[node * 3 + 2] = s2;
        if (node < NS) {
            g16[0 * NS + node] = __float2half(s0);
            g16[1 * NS + node] = __float2half(s1);
            g16[2 * NS + node] = __float2half(s2);
        }
    }
}

// ---------------------------------------------------------------------------
// Kernel 2: hybrid gather + masked mean.
// - First NS nodes served from a 228 KB fp16 smem table (cheap random LDS).
// - Remaining nodes served from the fp32 global table (L1tex wavefronts).
// Persistent-style: 148 blocks (1/SM), 1024 threads, even quad split.
// ---------------------------------------------------------------------------
__global__ void __launch_bounds__(1024, 1)
gather_kernel(const int* __restrict__ paths, float* __restrict__ out) {
    extern __shared__ __half s_tab[];  // [3][NS]

    const int tid = threadIdx.x;

    // Cooperative smem fill: 228000 B = 14250 float4
    {
        const float4* src = (const float4*)g16;
        float4*       dst = (float4*)s_tab;
        #pragma unroll 4
        for (int i = tid; i < SMEM_BYTES / 16; i += 1024)
            dst[i] = __ldg(src + i);
    }
    __syncthreads();

    const long long QT = N_PATHS / 4;  // 2.5M quads
    const long long q0 = (long long)blockIdx.x * QT / gridDim.x;
    const long long q1 = (long long)(blockIdx.x + 1) * QT / gridDim.x;

    for (long long q = q0 + tid; q < q1; q += 1024) {
        const int4* p4 = ((const int4*)paths) + q * 3;
        int4 v0 = __ldg(p4 + 0);
        int4 v1 = __ldg(p4 + 1);
        int4 v2 = __ldg(p4 + 2);

        int idx[12] = { v0.x, v0.y, v0.z, v0.w,
                        v1.x, v1.y, v1.z, v1.w,
                        v2.x, v2.y, v2.z, v2.w };

        float4 res;
        float* r = (float*)&res;

        #pragma unroll
        for (int k = 0; k < 4; k++) {
            float s = 0.0f;
            int   cnt = 0;
            #pragma unroll
            for (int l = 0; l < 3; l++) {
                int p = idx[k * 3 + l];
                if (p >= 0) {
                    if (p < NS)
                        s += __half2float(s_tab[l * NS + p]);
                    else
                        s += __ldg(&g_proj[p * 3 + l]);
                    cnt++;
                }
            }
            int len = (cnt > 0) ? cnt : 1;
            r[k] = s / (float)len;
        }

        ((float4*)out)[q] = res;
    }
}

// ---------------------------------------------------------------------------
// Launch. Inputs identified by element count:
//   30,000,000 -> paths (int32 [10M,3]); 12,800,000 -> node_feature; 384 -> W
// ---------------------------------------------------------------------------
extern "C" void kernel_launch(void* const* d_in, const int* in_sizes, int n_in,
                              void* d_out, int out_size) {
    const void*  paths_raw = nullptr;
    const float* nf        = nullptr;
    const float* W         = nullptr;

    for (int i = 0; i < n_in; i++) {
        if      (in_sizes[i] == N_PATHS * MAX_LEN)  paths_raw = d_in[i];
        else if (in_sizes[i] == N_NODES * HIDDEN)   nf        = (const float*)d_in[i];
        else if (in_sizes[i] == MAX_LEN * HIDDEN)   W         = (const float*)d_in[i];
    }

    float* out = (float*)d_out;

    // Opt in to >48KB dynamic smem (idempotent; not a stream-ordered op, so
    // it is graph-capture safe).
    static bool attr_done = false;
    if (!attr_done) {
        cudaFuncSetAttribute(gather_kernel,
                             cudaFuncAttributeMaxDynamicSharedMemorySize,
                             SMEM_BYTES);
        attr_done = true;
    }

    // proj: one warp per node
    {
        const int threads = 256;
        const int warpsPerBlock = threads / 32;
        const int blocks = (N_NODES + warpsPerBlock - 1) / warpsPerBlock;
        proj_kernel<<<blocks, threads>>>(nf, W);
    }

    // gather: persistent-style, 1 CTA per SM
    gather_kernel<<<148, 1024, SMEM_BYTES>>>((const int*)paths_raw, out);
}